// round 3
// baseline (speedup 1.0000x reference)
#include <cuda_runtime.h>
#include <math.h>

// Problem constants
#define B_   4
#define T_   2048
#define DM_  1024
#define H_   16
#define DH_  64
#define M_   (B_ * T_)          // 8192 rows for all GEMMs

// Scratch (device globals: allocation-free rule)
__device__ float g_q[M_ * DM_];
__device__ float g_k[M_ * DM_];
__device__ float g_v[M_ * DM_];
__device__ float g_y[M_ * DM_];

// ---------------------------------------------------------------------------
// SGEMM: C[M,N] = (A[M,K] @ W[N,K]^T + bias[N]) * scale
// BM=BN=128, BK=8, 256 threads, 8x8 microtile per thread.
// qkv_layout=1: write into [B,H,T,DH] layout (for Q/K/V); else row-major.
// ---------------------------------------------------------------------------
__global__ __launch_bounds__(256) void sgemm_kernel(
    const float* __restrict__ A,
    const float* __restrict__ W,
    const float* __restrict__ bias,
    float* __restrict__ C,
    float scale, int qkv_layout)
{
    const int K = DM_;
    const int N = DM_;
    __shared__ float As[8][128];
    __shared__ float Bs[8][128];

    const int tid = threadIdx.x;
    const int m0 = blockIdx.y * 128;
    const int n0 = blockIdx.x * 128;
    const int tm = tid >> 4;     // 0..15
    const int tn = tid & 15;     // 0..15

    const int lr = tid >> 1;         // 0..127 (row within tile for loads)
    const int lk = (tid & 1) * 4;    // 0 or 4

    const float* Aptr = A + (size_t)(m0 + lr) * K + lk;
    const float* Wptr = W + (size_t)(n0 + lr) * K + lk;

    float acc[8][8];
#pragma unroll
    for (int i = 0; i < 8; i++)
#pragma unroll
        for (int j = 0; j < 8; j++) acc[i][j] = 0.0f;

    for (int k0 = 0; k0 < K; k0 += 8) {
        float4 av = *(const float4*)(Aptr + k0);
        float4 wv = *(const float4*)(Wptr + k0);
        As[lk + 0][lr] = av.x; As[lk + 1][lr] = av.y;
        As[lk + 2][lr] = av.z; As[lk + 3][lr] = av.w;
        Bs[lk + 0][lr] = wv.x; Bs[lk + 1][lr] = wv.y;
        Bs[lk + 2][lr] = wv.z; Bs[lk + 3][lr] = wv.w;
        __syncthreads();

#pragma unroll
        for (int kk = 0; kk < 8; kk++) {
            float ar[8], br[8];
            *(float4*)(ar)     = *(const float4*)&As[kk][tm * 8];
            *(float4*)(ar + 4) = *(const float4*)&As[kk][tm * 8 + 4];
            *(float4*)(br)     = *(const float4*)&Bs[kk][tn * 8];
            *(float4*)(br + 4) = *(const float4*)&Bs[kk][tn * 8 + 4];
#pragma unroll
            for (int i = 0; i < 8; i++)
#pragma unroll
                for (int j = 0; j < 8; j++)
                    acc[i][j] += ar[i] * br[j];
        }
        __syncthreads();
    }

#pragma unroll
    for (int i = 0; i < 8; i++) {
        const int m = m0 + tm * 8 + i;
#pragma unroll
        for (int j = 0; j < 8; j++) {
            const int n = n0 + tn * 8 + j;
            float val = (acc[i][j] + bias[n]) * scale;
            if (qkv_layout) {
                const int b = m >> 11;          // /T_
                const int t = m & (T_ - 1);
                const int h = n >> 6;           // /DH_
                const int d = n & (DH_ - 1);
                C[(((size_t)(b * H_ + h) * T_) + t) * DH_ + d] = val;
            } else {
                C[(size_t)m * N + n] = val;
            }
        }
    }
}

// ---------------------------------------------------------------------------
// Flash attention, fp32, warp-per-query.
// grid: (T/8, H, B); block: 256 threads = 8 warps = 8 queries.
// K tile stored d-major (transposed) in shared, V tile k-major.
// ---------------------------------------------------------------------------
__global__ __launch_bounds__(256) void attn_kernel()
{
    __shared__ float Ks[64][65];   // [d][k], padded
    __shared__ float Vs[64][64];   // [k][d]

    const int tid  = threadIdx.x;
    const int warp = tid >> 5;
    const int lane = tid & 31;
    const int b = blockIdx.z;
    const int h = blockIdx.y;
    const int q = blockIdx.x * 8 + warp;
    const int qmax = blockIdx.x * 8 + 7;

    const size_t base = ((size_t)(b * H_ + h)) * T_ * DH_;

    // Load this warp's query row into registers (64 floats).
    float4 qv[16];
    {
        const float* qptr = g_q + base + (size_t)q * DH_;
#pragma unroll
        for (int i = 0; i < 16; i++) qv[i] = *(const float4*)(qptr + 4 * i);
    }

    float o0 = 0.0f, o1 = 0.0f;
    float mval = -1e30f, lsum = 0.0f;
    const unsigned FULL = 0xFFFFFFFFu;

    for (int c = 0; c <= qmax; c += 64) {
        // cooperative load: K chunk (transposed) and V chunk
#pragma unroll
        for (int i = 0; i < 4; i++) {
            const int idx = tid + i * 256;      // float4 index 0..1023
            const int kk = idx >> 4;            // key within chunk
            const int dd = (idx & 15) * 4;
            float4 kv = *(const float4*)(g_k + base + (size_t)(c + kk) * DH_ + dd);
            Ks[dd + 0][kk] = kv.x; Ks[dd + 1][kk] = kv.y;
            Ks[dd + 2][kk] = kv.z; Ks[dd + 3][kk] = kv.w;
            float4 vv = *(const float4*)(g_v + base + (size_t)(c + kk) * DH_ + dd);
            *(float4*)&Vs[kk][dd] = vv;
        }
        __syncthreads();

        // scores for keys (c+lane) and (c+lane+32)
        float s0 = 0.0f, s1 = 0.0f;
#pragma unroll
        for (int d4 = 0; d4 < 16; d4++) {
            const float4 qq = qv[d4];
            const int d = d4 * 4;
            s0 += qq.x * Ks[d][lane]     + qq.y * Ks[d + 1][lane]
                + qq.z * Ks[d + 2][lane] + qq.w * Ks[d + 3][lane];
            s1 += qq.x * Ks[d][lane + 32]     + qq.y * Ks[d + 1][lane + 32]
                + qq.z * Ks[d + 2][lane + 32] + qq.w * Ks[d + 3][lane + 32];
        }
        if (c + lane > q)      s0 = -1e30f;
        if (c + lane + 32 > q) s1 = -1e30f;

        // online softmax update
        float cm = fmaxf(s0, s1);
#pragma unroll
        for (int off = 16; off >= 1; off >>= 1)
            cm = fmaxf(cm, __shfl_xor_sync(FULL, cm, off));
        const float mnew = fmaxf(mval, cm);
        const float corr = __expf(mval - mnew);
        const float p0 = __expf(s0 - mnew);
        const float p1 = __expf(s1 - mnew);
        float ps = p0 + p1;
#pragma unroll
        for (int off = 16; off >= 1; off >>= 1)
            ps += __shfl_xor_sync(FULL, ps, off);
        lsum = lsum * corr + ps;
        o0 *= corr; o1 *= corr;
        mval = mnew;

        // PV: broadcast probabilities, accumulate output
#pragma unroll
        for (int kk = 0; kk < 32; kk++) {
            const float p = __shfl_sync(FULL, p0, kk);
            o0 += p * Vs[kk][lane];
            o1 += p * Vs[kk][lane + 32];
        }
#pragma unroll
        for (int kk = 0; kk < 32; kk++) {
            const float p = __shfl_sync(FULL, p1, kk);
            o0 += p * Vs[kk + 32][lane];
            o1 += p * Vs[kk + 32][lane + 32];
        }
        __syncthreads();
    }

    const float inv = 1.0f / lsum;
    // write to [B,T,DM] layout for the output projection
    float* yptr = g_y + ((size_t)(b * T_ + q)) * DM_ + h * DH_;
    yptr[lane]      = o0 * inv;
    yptr[lane + 32] = o1 * inv;
}

// ---------------------------------------------------------------------------
// Launch
// ---------------------------------------------------------------------------
extern "C" void kernel_launch(void* const* d_in, const int* in_sizes, int n_in,
                              void* d_out, int out_size)
{
    const float* x  = (const float*)d_in[0];
    const float* Wq = (const float*)d_in[1];
    const float* bq = (const float*)d_in[2];
    const float* Wk = (const float*)d_in[3];
    const float* bk = (const float*)d_in[4];
    const float* Wv = (const float*)d_in[5];
    const float* bv = (const float*)d_in[6];
    const float* Wo = (const float*)d_in[7];
    const float* bo = (const float*)d_in[8];
    float* out = (float*)d_out;

    float *pq, *pk, *pv, *py;
    cudaGetSymbolAddress((void**)&pq, g_q);
    cudaGetSymbolAddress((void**)&pk, g_k);
    cudaGetSymbolAddress((void**)&pv, g_v);
    cudaGetSymbolAddress((void**)&py, g_y);

    dim3 ggrid(DM_ / 128, M_ / 128);
    const float qscale = 0.125f;   // 1/sqrt(64)

    sgemm_kernel<<<ggrid, 256>>>(x, Wq, bq, pq, qscale, 1);
    sgemm_kernel<<<ggrid, 256>>>(x, Wk, bk, pk, 1.0f, 1);
    sgemm_kernel<<<ggrid, 256>>>(x, Wv, bv, pv, 1.0f, 1);

    dim3 agrid(T_ / 8, H_, B_);
    attn_kernel<<<agrid, 256>>>();

    sgemm_kernel<<<ggrid, 256>>>(py, Wo, bo, out, 1.0f, 0);
}

// round 9
// speedup vs baseline: 1.3805x; 1.3805x over previous
#include <cuda_runtime.h>
#include <stdint.h>
#include <math.h>

// Problem constants
#define B_   4
#define T_   2048
#define DM_  1024
#define H_   16
#define DH_  64
#define M_   (B_ * T_)          // 8192 rows for all GEMMs

// Scratch (device globals: allocation-free rule)
__device__ float g_q[M_ * DM_];
__device__ float g_k[M_ * DM_];
__device__ float g_v[M_ * DM_];
__device__ float g_y[M_ * DM_];        // attention output (tf32-rounded)
__device__ float g_xtf[M_ * DM_];      // tf32-rounded x
__device__ float g_wtf[4 * DM_ * DM_]; // tf32-rounded Wq,Wk,Wv,Wo

// ---------------------------------------------------------------------------
// Helpers
// ---------------------------------------------------------------------------
__device__ __forceinline__ uint32_t smem_u32(const void* p) {
    uint32_t a;
    asm("{ .reg .u64 t; cvta.to.shared.u64 t, %1; cvt.u32.u64 %0, t; }"
        : "=r"(a) : "l"(p));
    return a;
}

__device__ __forceinline__ float rtf32(float x) {
    float y;
    asm("cvt.rna.tf32.f32 %0, %1;" : "=f"(y) : "f"(x));
    return y;
}

__device__ __forceinline__ void mma_tf32_16x8x8(
    float* c, const uint32_t* a, const uint32_t* b)
{
    asm volatile(
        "mma.sync.aligned.m16n8k8.row.col.f32.tf32.tf32.f32 "
        "{%0,%1,%2,%3}, {%4,%5,%6,%7}, {%8,%9}, {%0,%1,%2,%3};"
        : "+f"(c[0]), "+f"(c[1]), "+f"(c[2]), "+f"(c[3])
        : "r"(a[0]), "r"(a[1]), "r"(a[2]), "r"(a[3]),
          "r"(b[0]), "r"(b[1]));
}

// ---------------------------------------------------------------------------
// tf32 rounding copy kernel
// ---------------------------------------------------------------------------
__global__ void __launch_bounds__(256) round_kernel(const float4* __restrict__ in,
                                                    float4* __restrict__ out, int n4) {
    int i = blockIdx.x * 256 + threadIdx.x;
    if (i < n4) {
        float4 v = in[i];
        v.x = rtf32(v.x); v.y = rtf32(v.y); v.z = rtf32(v.z); v.w = rtf32(v.w);
        out[i] = v;
    }
}

// ---------------------------------------------------------------------------
// mma.sync tf32 GEMM: C[M,N] = (A[M,K] @ W[N,K]^T + bias[N]) * scale
// CTA tile 128x128, 256 threads = 8 warps (2 m x 4 n), warp tile 64x32.
// m16n8k8 atoms, BK=32, 2-stage cp.async double buffer.
// SMEM row stride = 36 floats: 16B-aligned rows for cp.async, and fragment
// reads hit banks (4*g + tg + const) % 32 -> conflict-free.
// ---------------------------------------------------------------------------
#define RS          36                      // floats per smem row
#define MAT_FLOATS  (128 * RS)              // one 128x32 tile (padded)
#define STAGE_FLOATS (2 * MAT_FLOATS)       // A tile + W tile
#define GEMM_SMEM   (2 * STAGE_FLOATS * 4)  // 2 stages, bytes (73728)

__device__ __forceinline__ void load_stage(
    const float* __restrict__ A, const float* __restrict__ W,
    int m0, int n0, int chunk, uint32_t sbase, int tid)
{
    const uint32_t st = sbase + (uint32_t)(chunk & 1) * (STAGE_FLOATS * 4);
    const float* Ab = A + (size_t)m0 * DM_ + chunk * 32;
    const float* Wb = W + (size_t)n0 * DM_ + chunk * 32;
#pragma unroll
    for (int j = 0; j < 4; j++) {
        int idx = tid + j * 256;            // 0..1023
        int row = idx >> 3;                 // 0..127
        int c4  = (idx & 7) * 4;            // float col 0,4,..28
        uint32_t doff = (uint32_t)(row * RS + c4) * 4;
        asm volatile("cp.async.cg.shared.global [%0], [%1], 16;"
                     :: "r"(st + doff), "l"(Ab + (size_t)row * DM_ + c4) : "memory");
        asm volatile("cp.async.cg.shared.global [%0], [%1], 16;"
                     :: "r"(st + MAT_FLOATS * 4 + doff), "l"(Wb + (size_t)row * DM_ + c4) : "memory");
    }
}

__global__ void __launch_bounds__(256, 2) tgemm_kernel(
    const float* __restrict__ A,
    const float* __restrict__ W,
    const float* __restrict__ bias,
    float* __restrict__ C,
    float scale, int qkv_layout)
{
    extern __shared__ float sm[];
    const uint32_t sbase = smem_u32(sm);

    const int tid  = threadIdx.x;
    const int wid  = tid >> 5;
    const int lane = tid & 31;
    const int g    = lane >> 2;            // group 0..7
    const int tg   = lane & 3;             // 0..3
    const int m0 = blockIdx.y * 128;
    const int n0 = blockIdx.x * 128;
    const int m_w = (wid >> 2) * 64;       // warp m origin within tile
    const int n_w = (wid & 3) * 32;        // warp n origin within tile

    float acc[4][4][4];
#pragma unroll
    for (int i = 0; i < 4; i++)
#pragma unroll
        for (int j = 0; j < 4; j++)
#pragma unroll
            for (int r = 0; r < 4; r++) acc[i][j][r] = 0.0f;

    // prologue
    load_stage(A, W, m0, n0, 0, sbase, tid);
    asm volatile("cp.async.commit_group;" ::: "memory");

    for (int i = 0; i < 32; i++) {
        if (i + 1 < 32) load_stage(A, W, m0, n0, i + 1, sbase, tid);
        asm volatile("cp.async.commit_group;" ::: "memory");
        asm volatile("cp.async.wait_group 1;" ::: "memory");
        __syncthreads();

        const float* As = sm + (size_t)(i & 1) * STAGE_FLOATS;
        const float* Ws = As + MAT_FLOATS;
        const uint32_t* Au = (const uint32_t*)As;
        const uint32_t* Wu = (const uint32_t*)Ws;

#pragma unroll
        for (int ks = 0; ks < 4; ks++) {
            const int k = ks * 8;
            uint32_t af[4][4], bf[4][2];
#pragma unroll
            for (int ma = 0; ma < 4; ma++) {
                const int r = m_w + ma * 16 + g;
                af[ma][0] = Au[r * RS + k + tg];
                af[ma][1] = Au[(r + 8) * RS + k + tg];
                af[ma][2] = Au[r * RS + k + tg + 4];
                af[ma][3] = Au[(r + 8) * RS + k + tg + 4];
            }
#pragma unroll
            for (int na = 0; na < 4; na++) {
                const int n = n_w + na * 8 + g;
                bf[na][0] = Wu[n * RS + k + tg];
                bf[na][1] = Wu[n * RS + k + tg + 4];
            }
#pragma unroll
            for (int ma = 0; ma < 4; ma++)
#pragma unroll
                for (int na = 0; na < 4; na++)
                    mma_tf32_16x8x8(acc[ma][na], af[ma], bf[na]);
        }
        __syncthreads();
    }

    // ---- epilogue: registers -> global (bias + scale + optional layout) ----
#pragma unroll
    for (int ma = 0; ma < 4; ma++) {
        const int mA = m0 + m_w + ma * 16 + g;
#pragma unroll
        for (int na = 0; na < 4; na++) {
            const int n = n0 + n_w + na * 8 + tg * 2;
            const float b0 = bias[n], b1 = bias[n + 1];
#pragma unroll
            for (int half = 0; half < 2; half++) {
                const int m = mA + half * 8;
                float2 v;
                v.x = (acc[ma][na][half * 2 + 0] + b0) * scale;
                v.y = (acc[ma][na][half * 2 + 1] + b1) * scale;
                if (qkv_layout) {
                    const int b  = m >> 11;          // / T_
                    const int t  = m & (T_ - 1);
                    const int h  = n >> 6;           // / DH_
                    const int d  = n & (DH_ - 1);
                    *(float2*)&C[(((size_t)(b * H_ + h) * T_) + t) * DH_ + d] = v;
                } else {
                    *(float2*)&C[(size_t)m * DM_ + n] = v;
                }
            }
        }
    }
}

// ---------------------------------------------------------------------------
// Flash attention, fp32, warp-per-query (unchanged; writes tf32-rounded y)
// ---------------------------------------------------------------------------
__global__ void __launch_bounds__(256) attn_kernel()
{
    __shared__ float Ks[64][65];   // [d][k], padded
    __shared__ float Vs[64][64];   // [k][d]

    const int tid  = threadIdx.x;
    const int warp = tid >> 5;
    const int lane = tid & 31;
    const int b = blockIdx.z;
    const int h = blockIdx.y;
    const int q = blockIdx.x * 8 + warp;
    const int qmax = blockIdx.x * 8 + 7;

    const size_t base = ((size_t)(b * H_ + h)) * T_ * DH_;

    float4 qv[16];
    {
        const float* qptr = g_q + base + (size_t)q * DH_;
#pragma unroll
        for (int i = 0; i < 16; i++) qv[i] = *(const float4*)(qptr + 4 * i);
    }

    float o0 = 0.0f, o1 = 0.0f;
    float mval = -1e30f, lsum = 0.0f;
    const unsigned FULL = 0xFFFFFFFFu;

    for (int c = 0; c <= qmax; c += 64) {
#pragma unroll
        for (int i = 0; i < 4; i++) {
            const int idx = tid + i * 256;
            const int kk = idx >> 4;
            const int dd = (idx & 15) * 4;
            float4 kv = *(const float4*)(g_k + base + (size_t)(c + kk) * DH_ + dd);
            Ks[dd + 0][kk] = kv.x; Ks[dd + 1][kk] = kv.y;
            Ks[dd + 2][kk] = kv.z; Ks[dd + 3][kk] = kv.w;
            float4 vv = *(const float4*)(g_v + base + (size_t)(c + kk) * DH_ + dd);
            *(float4*)&Vs[kk][dd] = vv;
        }
        __syncthreads();

        float s0 = 0.0f, s1 = 0.0f;
#pragma unroll
        for (int d4 = 0; d4 < 16; d4++) {
            const float4 qq = qv[d4];
            const int d = d4 * 4;
            s0 += qq.x * Ks[d][lane]     + qq.y * Ks[d + 1][lane]
                + qq.z * Ks[d + 2][lane] + qq.w * Ks[d + 3][lane];
            s1 += qq.x * Ks[d][lane + 32]     + qq.y * Ks[d + 1][lane + 32]
                + qq.z * Ks[d + 2][lane + 32] + qq.w * Ks[d + 3][lane + 32];
        }
        if (c + lane > q)      s0 = -1e30f;
        if (c + lane + 32 > q) s1 = -1e30f;

        float cm = fmaxf(s0, s1);
#pragma unroll
        for (int off = 16; off >= 1; off >>= 1)
            cm = fmaxf(cm, __shfl_xor_sync(FULL, cm, off));
        const float mnew = fmaxf(mval, cm);
        const float corr = __expf(mval - mnew);
        const float p0 = __expf(s0 - mnew);
        const float p1 = __expf(s1 - mnew);
        float ps = p0 + p1;
#pragma unroll
        for (int off = 16; off >= 1; off >>= 1)
            ps += __shfl_xor_sync(FULL, ps, off);
        lsum = lsum * corr + ps;
        o0 *= corr; o1 *= corr;
        mval = mnew;

#pragma unroll
        for (int kk = 0; kk < 32; kk++) {
            const float p = __shfl_sync(FULL, p0, kk);
            o0 += p * Vs[kk][lane];
            o1 += p * Vs[kk][lane + 32];
        }
#pragma unroll
        for (int kk = 0; kk < 32; kk++) {
            const float p = __shfl_sync(FULL, p1, kk);
            o0 += p * Vs[kk + 32][lane];
            o1 += p * Vs[kk + 32][lane + 32];
        }
        __syncthreads();
    }

    const float inv = 1.0f / lsum;
    // write tf32-rounded y in [B,T,DM] layout for the tf32 output projection
    float* yptr = g_y + ((size_t)(b * T_ + q)) * DM_ + h * DH_;
    yptr[lane]      = rtf32(o0 * inv);
    yptr[lane + 32] = rtf32(o1 * inv);
}

// ---------------------------------------------------------------------------
// Launch
// ---------------------------------------------------------------------------
extern "C" void kernel_launch(void* const* d_in, const int* in_sizes, int n_in,
                              void* d_out, int out_size)
{
    const float* x  = (const float*)d_in[0];
    const float* Wq = (const float*)d_in[1];
    const float* bq = (const float*)d_in[2];
    const float* Wk = (const float*)d_in[3];
    const float* bk = (const float*)d_in[4];
    const float* Wv = (const float*)d_in[5];
    const float* bv = (const float*)d_in[6];
    const float* Wo = (const float*)d_in[7];
    const float* bo = (const float*)d_in[8];
    float* out = (float*)d_out;

    float *pq, *pk, *pv, *py, *pxtf, *pwtf;
    cudaGetSymbolAddress((void**)&pq, g_q);
    cudaGetSymbolAddress((void**)&pk, g_k);
    cudaGetSymbolAddress((void**)&pv, g_v);
    cudaGetSymbolAddress((void**)&py, g_y);
    cudaGetSymbolAddress((void**)&pxtf, g_xtf);
    cudaGetSymbolAddress((void**)&pwtf, g_wtf);

    static int smem_set = 0;
    if (!smem_set) {
        cudaFuncSetAttribute(tgemm_kernel,
                             cudaFuncAttributeMaxDynamicSharedMemorySize, GEMM_SMEM);
        smem_set = 1;
    }

    const int NW = DM_ * DM_;
    // round inputs to tf32 (rna, so HMMA's tf32 view is exact)
    round_kernel<<<(M_ * DM_ / 4 + 255) / 256, 256>>>((const float4*)x, (float4*)pxtf, M_ * DM_ / 4);
    round_kernel<<<(NW / 4 + 255) / 256, 256>>>((const float4*)Wq, (float4*)(pwtf + 0 * NW), NW / 4);
    round_kernel<<<(NW / 4 + 255) / 256, 256>>>((const float4*)Wk, (float4*)(pwtf + 1 * NW), NW / 4);
    round_kernel<<<(NW / 4 + 255) / 256, 256>>>((const float4*)Wv, (float4*)(pwtf + 2 * NW), NW / 4);
    round_kernel<<<(NW / 4 + 255) / 256, 256>>>((const float4*)Wo, (float4*)(pwtf + 3 * NW), NW / 4);

    dim3 ggrid(DM_ / 128, M_ / 128);     // (8, 64)
    const float qscale = 0.125f;         // 1/sqrt(64)

    tgemm_kernel<<<ggrid, 256, GEMM_SMEM>>>(pxtf, pwtf + 0 * NW, bq, pq, qscale, 1);
    tgemm_kernel<<<ggrid, 256, GEMM_SMEM>>>(pxtf, pwtf + 1 * NW, bk, pk, 1.0f, 1);
    tgemm_kernel<<<ggrid, 256, GEMM_SMEM>>>(pxtf, pwtf + 2 * NW, bv, pv, 1.0f, 1);

    dim3 agrid(T_ / 8, H_, B_);
    attn_kernel<<<agrid, 256>>>();

    tgemm_kernel<<<ggrid, 256, GEMM_SMEM>>>(py, pwtf + 3 * NW, bo, out, 1.0f, 0);
}

// round 10
// speedup vs baseline: 8.6295x; 6.2509x over previous
#include <cuda_runtime.h>
#include <cuda_fp16.h>
#include <stdint.h>
#include <math.h>

// Problem constants
#define B_   4
#define T_   2048
#define DM_  1024
#define H_   16
#define DH_  64
#define M_   (B_ * T_)          // 8192 rows for all GEMMs

// Scratch (device globals: allocation-free rule)
__device__ __half g_xh[M_ * DM_];        // fp16 x
__device__ __half g_wh[4 * DM_ * DM_];   // fp16 Wq,Wk,Wv,Wo
__device__ __half g_q[M_ * DM_];         // [B,H,T,DH], pre-scaled by 1/8
__device__ __half g_k[M_ * DM_];
__device__ __half g_v[M_ * DM_];
__device__ __half g_y[M_ * DM_];         // attention out, [B,T,DM]

// ---------------------------------------------------------------------------
// Helpers
// ---------------------------------------------------------------------------
__device__ __forceinline__ uint32_t smem_u32(const void* p) {
    uint32_t a;
    asm("{ .reg .u64 t; cvta.to.shared.u64 t, %1; cvt.u32.u64 %0, t; }"
        : "=r"(a) : "l"(p));
    return a;
}

__device__ __forceinline__ void mma_f16_16x8x16(
    float* c, const uint32_t* a, uint32_t b0, uint32_t b1)
{
    asm volatile(
        "mma.sync.aligned.m16n8k16.row.col.f32.f16.f16.f32 "
        "{%0,%1,%2,%3}, {%4,%5,%6,%7}, {%8,%9}, {%0,%1,%2,%3};"
        : "+f"(c[0]), "+f"(c[1]), "+f"(c[2]), "+f"(c[3])
        : "r"(a[0]), "r"(a[1]), "r"(a[2]), "r"(a[3]), "r"(b0), "r"(b1));
}

// ---------------------------------------------------------------------------
// fp32 -> fp16 conversion kernel
// ---------------------------------------------------------------------------
__global__ void __launch_bounds__(256) f2h_kernel(const float4* __restrict__ in,
                                                  __half2* __restrict__ out, int n4) {
    int i = blockIdx.x * 256 + threadIdx.x;
    if (i < n4) {
        float4 v = in[i];
        out[2 * i]     = __floats2half2_rn(v.x, v.y);
        out[2 * i + 1] = __floats2half2_rn(v.z, v.w);
    }
}

// ---------------------------------------------------------------------------
// fp16 mma GEMM: C[M,N] = (A[M,K] @ W[N,K]^T + bias[N]) * scale
// CTA tile 128x128, 256 threads = 8 warps (2m x 4n), warp tile 64x32.
// m16n8k16 atoms, BK=32, 2-stage cp.async double buffer.
// SMEM rows: 40 halfs (80B) -> fragment LDS banks (20g+tg+c)%32 distinct.
// ---------------------------------------------------------------------------
#define RSH   40                         // halfs per smem row
#define MATB  (128 * 80)                 // bytes per 128x32 half tile (padded)
#define STGB  (2 * MATB)                 // A + W
#define GSMEM (2 * STGB)                 // 2 stages = 40960 B

__device__ __forceinline__ void load_stage_h(
    const __half* __restrict__ A, const __half* __restrict__ W,
    int m0, int n0, int chunk, uint32_t sbase, int tid)
{
    const uint32_t st = sbase + (uint32_t)(chunk & 1) * STGB;
#pragma unroll
    for (int j = 0; j < 2; j++) {
        int idx = tid + j * 256;             // 0..511
        int row = idx >> 2;                  // 0..127
        int ch  = idx & 3;                   // 16B chunk in row
        uint32_t dst = st + (uint32_t)(row * 80 + ch * 16);
        const char* srcA = (const char*)(A + (size_t)(m0 + row) * DM_ + chunk * 32) + ch * 16;
        asm volatile("cp.async.cg.shared.global [%0], [%1], 16;"
                     :: "r"(dst), "l"(srcA) : "memory");
        const char* srcW = (const char*)(W + (size_t)(n0 + row) * DM_ + chunk * 32) + ch * 16;
        asm volatile("cp.async.cg.shared.global [%0], [%1], 16;"
                     :: "r"(dst + MATB), "l"(srcW) : "memory");
    }
}

__global__ void __launch_bounds__(256, 2) hgemm_kernel(
    const __half* __restrict__ A,
    const __half* __restrict__ W,
    const float* __restrict__ bias,
    float* __restrict__ Cf,        // used when qkv_layout == 0
    __half* __restrict__ Ch,       // used when qkv_layout == 1
    float scale, int qkv_layout)
{
    extern __shared__ char smraw[];
    const uint32_t sbase = smem_u32(smraw);

    const int tid  = threadIdx.x;
    const int wid  = tid >> 5;
    const int lane = tid & 31;
    const int g    = lane >> 2;
    const int tg   = lane & 3;
    const int m0 = blockIdx.y * 128;
    const int n0 = blockIdx.x * 128;
    const int m_w = (wid >> 2) * 64;
    const int n_w = (wid & 3) * 32;

    float acc[4][4][4];
#pragma unroll
    for (int i = 0; i < 4; i++)
#pragma unroll
        for (int j = 0; j < 4; j++)
#pragma unroll
            for (int r = 0; r < 4; r++) acc[i][j][r] = 0.0f;

    load_stage_h(A, W, m0, n0, 0, sbase, tid);
    asm volatile("cp.async.commit_group;" ::: "memory");

    for (int i = 0; i < 32; i++) {
        if (i + 1 < 32) load_stage_h(A, W, m0, n0, i + 1, sbase, tid);
        asm volatile("cp.async.commit_group;" ::: "memory");
        asm volatile("cp.async.wait_group 1;" ::: "memory");
        __syncthreads();

        const uint32_t* Sw = (const uint32_t*)(smraw + (size_t)(i & 1) * STGB);
        const uint32_t* Ww = Sw + MATB / 4;

#pragma unroll
        for (int ks = 0; ks < 2; ks++) {
            uint32_t af[4][4], bf[4][2];
#pragma unroll
            for (int ma = 0; ma < 4; ma++) {
                const int r = m_w + ma * 16 + g;
                const int base = r * 20 + ks * 8 + tg;
                af[ma][0] = Sw[base];
                af[ma][1] = Sw[base + 160];     // (r+8)*20
                af[ma][2] = Sw[base + 4];
                af[ma][3] = Sw[base + 164];
            }
#pragma unroll
            for (int na = 0; na < 4; na++) {
                const int n = n_w + na * 8 + g;
                const int wb = n * 20 + ks * 8 + tg;
                bf[na][0] = Ww[wb];
                bf[na][1] = Ww[wb + 4];
            }
#pragma unroll
            for (int ma = 0; ma < 4; ma++)
#pragma unroll
                for (int na = 0; na < 4; na++)
                    mma_f16_16x8x16(acc[ma][na], af[ma], bf[na][0], bf[na][1]);
        }
        __syncthreads();
    }

    // epilogue: regs -> global
#pragma unroll
    for (int ma = 0; ma < 4; ma++) {
        const int mA = m0 + m_w + ma * 16 + g;
#pragma unroll
        for (int na = 0; na < 4; na++) {
            const int n = n0 + n_w + na * 8 + tg * 2;
            const float b0 = bias[n], b1 = bias[n + 1];
#pragma unroll
            for (int half_i = 0; half_i < 2; half_i++) {
                const int m = mA + half_i * 8;
                float v0 = (acc[ma][na][half_i * 2 + 0] + b0) * scale;
                float v1 = (acc[ma][na][half_i * 2 + 1] + b1) * scale;
                if (qkv_layout) {
                    const int b = m >> 11;
                    const int t = m & (T_ - 1);
                    const int h = n >> 6;
                    const int d = n & (DH_ - 1);
                    *(__half2*)&Ch[(((size_t)(b * H_ + h) * T_) + t) * DH_ + d] =
                        __floats2half2_rn(v0, v1);
                } else {
                    float2 v; v.x = v0; v.y = v1;
                    *(float2*)&Cf[(size_t)m * DM_ + n] = v;
                }
            }
        }
    }
}

// ---------------------------------------------------------------------------
// Tensor-core flash attention (fp16 mma, fp32 accum/softmax).
// Grid: (16 q-blocks, H, B); block 256 = 8 warps; CTA = 128 queries.
// Warp owns 16 q rows. KV tiles of 64 keys.
//   QK:  A = Q frags (regs), B = Ks[key][d]  (pad-8 rows -> conflict-free)
//   PV:  A = P frags (via SMEM Ps), B = Vst[d][key] (transposed, pad-8)
// ---------------------------------------------------------------------------
#define RKH 72
#define RPH 72

__global__ void __launch_bounds__(256, 2) attn_kernel()
{
    __shared__ __align__(16) __half Ks[64 * RKH];
    __shared__ __align__(16) __half Vst[64 * RKH];
    __shared__ __align__(16) __half Ps[8 * 16 * RPH];

    const int tid  = threadIdx.x;
    const int w    = tid >> 5;
    const int lane = tid & 31;
    const int g    = lane >> 2;
    const int tg   = lane & 3;
    const int b  = blockIdx.z;
    const int h  = blockIdx.y;
    const int qb = (gridDim.x - 1) - blockIdx.x;   // heaviest blocks first
    const int W0 = qb * 128 + w * 16;              // warp's first q row

    const size_t base = ((size_t)(b * H_ + h)) * T_ * DH_;

    // Q fragments: 4 k-steps (d=64), 4 regs each (rows g, g+8)
    uint32_t aq[4][4];
    {
        const uint32_t* Qg = (const uint32_t*)(g_q + base);
        const int r0 = (W0 + g) * 32;       // words per row = 32
        const int r1 = (W0 + g + 8) * 32;
#pragma unroll
        for (int ks = 0; ks < 4; ks++) {
            const int o = ks * 8 + tg;
            aq[ks][0] = Qg[r0 + o];
            aq[ks][1] = Qg[r1 + o];
            aq[ks][2] = Qg[r0 + o + 4];
            aq[ks][3] = Qg[r1 + o + 4];
        }
    }

    float o[8][4];
#pragma unroll
    for (int i = 0; i < 8; i++)
#pragma unroll
        for (int r = 0; r < 4; r++) o[i][r] = 0.0f;
    float m0 = -1e30f, m1 = -1e30f, l0 = 0.0f, l1 = 0.0f;
    const unsigned FULL = 0xFFFFFFFFu;

    const int ntiles = 2 * qb + 2;
    for (int t = 0; t < ntiles; t++) {
        const int c = t * 64;
        __syncthreads();
        // load K tile: Ks[key][d]
#pragma unroll
        for (int j = 0; j < 4; j++) {
            int idx = tid + j * 256;             // 0..1023
            int key = idx >> 4;
            int c8  = (idx & 15) * 4;
            *(uint2*)&Ks[key * RKH + c8] =
                *(const uint2*)&g_k[base + (size_t)(c + key) * DH_ + c8];
        }
        // load V tile transposed: Vst[d][key]
#pragma unroll
        for (int j = 0; j < 8; j++) {
            int idx = tid + j * 256;             // 0..2047
            int key = idx >> 5;
            int d2  = (idx & 31) * 2;
            __half2 vv = *(const __half2*)&g_v[base + (size_t)(c + key) * DH_ + d2];
            Vst[d2 * RKH + key]       = __low2half(vv);
            Vst[(d2 + 1) * RKH + key] = __high2half(vv);
        }
        __syncthreads();

        if (c <= W0 + 15) {     // warp has at least one unmasked key
            // ---- QK^T ----
            float s[8][4];
#pragma unroll
            for (int i = 0; i < 8; i++)
#pragma unroll
                for (int r = 0; r < 4; r++) s[i][r] = 0.0f;
            const uint32_t* Kw = (const uint32_t*)Ks;
#pragma unroll
            for (int ks = 0; ks < 4; ks++) {
#pragma unroll
                for (int na = 0; na < 8; na++) {
                    const int n = na * 8 + g;
                    const int wb = n * (RKH / 2) + ks * 8 + tg;
                    mma_f16_16x8x16(s[na], aq[ks], Kw[wb], Kw[wb + 4]);
                }
            }
            // ---- causal mask (only near diagonal) ----
            if (c + 63 > W0) {
#pragma unroll
                for (int na = 0; na < 8; na++) {
                    const int key0 = c + na * 8 + tg * 2;
                    if (key0 > W0 + g)          s[na][0] = -1e30f;
                    if (key0 + 1 > W0 + g)      s[na][1] = -1e30f;
                    if (key0 > W0 + g + 8)      s[na][2] = -1e30f;
                    if (key0 + 1 > W0 + g + 8)  s[na][3] = -1e30f;
                }
            }
            // ---- online softmax (rows g and g+8) ----
            float mx0 = -1e30f, mx1 = -1e30f;
#pragma unroll
            for (int na = 0; na < 8; na++) {
                mx0 = fmaxf(mx0, fmaxf(s[na][0], s[na][1]));
                mx1 = fmaxf(mx1, fmaxf(s[na][2], s[na][3]));
            }
            mx0 = fmaxf(mx0, __shfl_xor_sync(FULL, mx0, 1));
            mx0 = fmaxf(mx0, __shfl_xor_sync(FULL, mx0, 2));
            mx1 = fmaxf(mx1, __shfl_xor_sync(FULL, mx1, 1));
            mx1 = fmaxf(mx1, __shfl_xor_sync(FULL, mx1, 2));
            const float mn0 = fmaxf(m0, mx0);
            const float mn1 = fmaxf(m1, mx1);
            const float cor0 = __expf(m0 - mn0);
            const float cor1 = __expf(m1 - mn1);
            float sum0 = 0.0f, sum1 = 0.0f;
            __half* Pw = Ps + w * (16 * RPH);
#pragma unroll
            for (int na = 0; na < 8; na++) {
                float p00 = __expf(s[na][0] - mn0);
                float p01 = __expf(s[na][1] - mn0);
                float p10 = __expf(s[na][2] - mn1);
                float p11 = __expf(s[na][3] - mn1);
                sum0 += p00 + p01;
                sum1 += p10 + p11;
                const int col = na * 8 + tg * 2;
                *(__half2*)&Pw[g * RPH + col]       = __floats2half2_rn(p00, p01);
                *(__half2*)&Pw[(g + 8) * RPH + col] = __floats2half2_rn(p10, p11);
            }
            sum0 += __shfl_xor_sync(FULL, sum0, 1);
            sum0 += __shfl_xor_sync(FULL, sum0, 2);
            sum1 += __shfl_xor_sync(FULL, sum1, 1);
            sum1 += __shfl_xor_sync(FULL, sum1, 2);
            l0 = l0 * cor0 + sum0;
            l1 = l1 * cor1 + sum1;
#pragma unroll
            for (int na = 0; na < 8; na++) {
                o[na][0] *= cor0; o[na][1] *= cor0;
                o[na][2] *= cor1; o[na][3] *= cor1;
            }
            m0 = mn0; m1 = mn1;
            __syncwarp();
            // ---- PV ----
            const uint32_t* Pww = (const uint32_t*)Pw;
            const uint32_t* Vw  = (const uint32_t*)Vst;
#pragma unroll
            for (int ks2 = 0; ks2 < 4; ks2++) {
                uint32_t pa[4];
                const int pb = ks2 * 8 + tg;
                pa[0] = Pww[g * (RPH / 2) + pb];
                pa[1] = Pww[(g + 8) * (RPH / 2) + pb];
                pa[2] = Pww[g * (RPH / 2) + pb + 4];
                pa[3] = Pww[(g + 8) * (RPH / 2) + pb + 4];
#pragma unroll
                for (int na = 0; na < 8; na++) {
                    const int n = na * 8 + g;
                    const int wb = n * (RKH / 2) + ks2 * 8 + tg;
                    mma_f16_16x8x16(o[na], pa, Vw[wb], Vw[wb + 4]);
                }
            }
        }
    }

    // ---- write y [B,T,DM] as fp16 ----
    const float inv0 = 1.0f / l0;
    const float inv1 = 1.0f / l1;
    const int q0 = W0 + g;
    const int q1 = W0 + g + 8;
    __half* y0 = g_y + ((size_t)(b * T_ + q0)) * DM_ + h * DH_;
    __half* y1 = g_y + ((size_t)(b * T_ + q1)) * DM_ + h * DH_;
#pragma unroll
    for (int na = 0; na < 8; na++) {
        const int d = na * 8 + tg * 2;
        *(__half2*)&y0[d] = __floats2half2_rn(o[na][0] * inv0, o[na][1] * inv0);
        *(__half2*)&y1[d] = __floats2half2_rn(o[na][2] * inv1, o[na][3] * inv1);
    }
}

// ---------------------------------------------------------------------------
// Launch
// ---------------------------------------------------------------------------
extern "C" void kernel_launch(void* const* d_in, const int* in_sizes, int n_in,
                              void* d_out, int out_size)
{
    const float* x  = (const float*)d_in[0];
    const float* Wq = (const float*)d_in[1];
    const float* bq = (const float*)d_in[2];
    const float* Wk = (const float*)d_in[3];
    const float* bk = (const float*)d_in[4];
    const float* Wv = (const float*)d_in[5];
    const float* bv = (const float*)d_in[6];
    const float* Wo = (const float*)d_in[7];
    const float* bo = (const float*)d_in[8];
    float* out = (float*)d_out;

    __half *pxh, *pwh, *pq, *pk, *pv, *py;
    cudaGetSymbolAddress((void**)&pxh, g_xh);
    cudaGetSymbolAddress((void**)&pwh, g_wh);
    cudaGetSymbolAddress((void**)&pq, g_q);
    cudaGetSymbolAddress((void**)&pk, g_k);
    cudaGetSymbolAddress((void**)&pv, g_v);
    cudaGetSymbolAddress((void**)&py, g_y);

    static int smem_set = 0;
    if (!smem_set) {
        cudaFuncSetAttribute(hgemm_kernel,
                             cudaFuncAttributeMaxDynamicSharedMemorySize, GSMEM);
        smem_set = 1;
    }

    const int NW = DM_ * DM_;
    // fp32 -> fp16 conversions
    f2h_kernel<<<(M_ * DM_ / 4 + 255) / 256, 256>>>((const float4*)x, (__half2*)pxh, M_ * DM_ / 4);
    f2h_kernel<<<(NW / 4 + 255) / 256, 256>>>((const float4*)Wq, (__half2*)(pwh + 0 * NW), NW / 4);
    f2h_kernel<<<(NW / 4 + 255) / 256, 256>>>((const float4*)Wk, (__half2*)(pwh + 1 * NW), NW / 4);
    f2h_kernel<<<(NW / 4 + 255) / 256, 256>>>((const float4*)Wv, (__half2*)(pwh + 2 * NW), NW / 4);
    f2h_kernel<<<(NW / 4 + 255) / 256, 256>>>((const float4*)Wo, (__half2*)(pwh + 3 * NW), NW / 4);

    dim3 ggrid(DM_ / 128, M_ / 128);     // (8, 64)
    const float qscale = 0.125f;         // 1/sqrt(64), folded into Q

    hgemm_kernel<<<ggrid, 256, GSMEM>>>(pxh, pwh + 0 * NW, bq, nullptr, pq, qscale, 1);
    hgemm_kernel<<<ggrid, 256, GSMEM>>>(pxh, pwh + 1 * NW, bk, nullptr, pk, 1.0f, 1);
    hgemm_kernel<<<ggrid, 256, GSMEM>>>(pxh, pwh + 2 * NW, bv, nullptr, pv, 1.0f, 1);

    dim3 agrid(T_ / 128, H_, B_);        // (16, 16, 4)
    attn_kernel<<<agrid, 256>>>();

    hgemm_kernel<<<ggrid, 256, GSMEM>>>(py, pwh + 3 * NW, bo, out, nullptr, 1.0f, 0);
}

// round 11
// speedup vs baseline: 12.7445x; 1.4768x over previous
#include <cuda_runtime.h>
#include <cuda_fp16.h>
#include <stdint.h>
#include <math.h>

// Problem constants
#define B_   4
#define T_   2048
#define DM_  1024
#define H_   16
#define DH_  64
#define M_   (B_ * T_)
#define NW_  (DM_ * DM_)

// Scratch (device globals: allocation-free rule)
__device__ __half g_xh[M_ * DM_];        // fp16 x
__device__ __half g_wh[4 * NW_];         // fp16 Wq,Wk,Wv,Wo
__device__ __half g_q[M_ * DM_];         // [B,H,T,DH], pre-scaled by 1/8
__device__ __half g_k[M_ * DM_];
__device__ __half g_v[M_ * DM_];
__device__ __half g_y[M_ * DM_];         // attention out, [B,T,DM]

// ---------------------------------------------------------------------------
// Helpers
// ---------------------------------------------------------------------------
__device__ __forceinline__ uint32_t smem_u32(const void* p) {
    uint32_t a;
    asm("{ .reg .u64 t; cvta.to.shared.u64 t, %1; cvt.u32.u64 %0, t; }"
        : "=r"(a) : "l"(p));
    return a;
}

__device__ __forceinline__ const char* to_global(const void* p) {
    uint64_t g;
    asm("cvta.to.global.u64 %0, %1;" : "=l"(g) : "l"(p));
    return (const char*)g;
}

__device__ __forceinline__ void mma_f16_16x8x16(
    float* c, const uint32_t* a, uint32_t b0, uint32_t b1)
{
    asm volatile(
        "mma.sync.aligned.m16n8k16.row.col.f32.f16.f16.f32 "
        "{%0,%1,%2,%3}, {%4,%5,%6,%7}, {%8,%9}, {%0,%1,%2,%3};"
        : "+f"(c[0]), "+f"(c[1]), "+f"(c[2]), "+f"(c[3])
        : "r"(a[0]), "r"(a[1]), "r"(a[2]), "r"(a[3]), "r"(b0), "r"(b1));
}

#define LDSM_X4(r0, r1, r2, r3, a) \
    asm volatile("ldmatrix.sync.aligned.m8n8.x4.shared.b16 {%0,%1,%2,%3}, [%4];" \
                 : "=r"(r0), "=r"(r1), "=r"(r2), "=r"(r3) : "r"(a))
#define LDSM_X4T(r0, r1, r2, r3, a) \
    asm volatile("ldmatrix.sync.aligned.m8n8.x4.trans.shared.b16 {%0,%1,%2,%3}, [%4];" \
                 : "=r"(r0), "=r"(r1), "=r"(r2), "=r"(r3) : "r"(a))
#define CP16(dst, src) \
    asm volatile("cp.async.cg.shared.global [%0], [%1], 16;" :: "r"(dst), "l"(src) : "memory")
#define CP_COMMIT() asm volatile("cp.async.commit_group;" ::: "memory")
#define CP_WAIT1()  asm volatile("cp.async.wait_group 1;" ::: "memory")

__device__ __forceinline__ uint32_t packh2(float a, float b) {
    __half2 h = __floats2half2_rn(a, b);
    return *(uint32_t*)&h;
}

// ---------------------------------------------------------------------------
// Fused fp32 -> fp16 conversion (x + all 4 weights in one launch)
// ---------------------------------------------------------------------------
__global__ void __launch_bounds__(256) f2h_all(
    const float4* __restrict__ x,  const float4* __restrict__ wq,
    const float4* __restrict__ wk, const float4* __restrict__ wv,
    const float4* __restrict__ wo, __half2* __restrict__ xh,
    __half2* __restrict__ wh)
{
    int i = blockIdx.x * 256 + threadIdx.x;
    const float4* src;
    __half2* dst;
    if (i < 2097152) {                       // x: 8M floats = 2M float4
        src = x + i;
        dst = xh + 2 * (size_t)i;
    } else {
        int j = i - 2097152;                 // weights: 4 x 256K float4
        int w = j >> 18, off = j & 0x3FFFF;
        const float4* ws = (w == 0) ? wq : (w == 1) ? wk : (w == 2) ? wv : wo;
        src = ws + off;
        dst = wh + (size_t)w * 524288 + 2 * (size_t)off;
    }
    float4 v = *src;
    dst[0] = __floats2half2_rn(v.x, v.y);
    dst[1] = __floats2half2_rn(v.z, v.w);
}

// ---------------------------------------------------------------------------
// fp16 mma GEMM core: C[M,N] = (A[M,K] @ W[N,K]^T + bias[N]) * scale
// CTA tile 128x128, 8 warps (2m x 4n), warp tile 64x32, m16n8k16.
// BK=32, 3-stage cp.async, ldmatrix fragment loads (80B rows, conflict-free).
// ---------------------------------------------------------------------------
#define MATB  (128 * 80)                 // bytes per padded 128x32 half tile
#define STGB  (2 * MATB)                 // A + W per stage
#define GSMEM (3 * STGB)                 // 61440 B

__device__ __forceinline__ void load_stage_h(
    const __half* __restrict__ A, const __half* __restrict__ W,
    int m0, int n0, int chunk, uint32_t sbase, int tid)
{
    const uint32_t st = sbase + (uint32_t)(chunk % 3) * STGB;
#pragma unroll
    for (int j = 0; j < 2; j++) {
        int idx = tid + j * 256;             // 0..511
        int row = idx >> 2;                  // 0..127
        int ch  = idx & 3;                   // 16B chunk
        uint32_t dst = st + (uint32_t)(row * 80 + ch * 16);
        CP16(dst, to_global(A + (size_t)(m0 + row) * DM_ + chunk * 32) + ch * 16);
        CP16(dst + MATB, to_global(W + (size_t)(n0 + row) * DM_ + chunk * 32) + ch * 16);
    }
}

__device__ __forceinline__ void gemm_core(
    const __half* __restrict__ A, const __half* __restrict__ W,
    const float* __restrict__ bias, float* __restrict__ Cf,
    __half* __restrict__ Ch, float scale, int qkv_layout, char* smraw)
{
    const uint32_t sbase = smem_u32(smraw);
    const int tid  = threadIdx.x;
    const int wid  = tid >> 5;
    const int lane = tid & 31;
    const int g    = lane >> 2;
    const int tg   = lane & 3;
    const int m0 = blockIdx.y * 128;
    const int n0 = blockIdx.x * 128;
    const int m_w = (wid >> 2) * 64;
    const int n_w = (wid & 3) * 32;

    float acc[4][4][4];
#pragma unroll
    for (int i = 0; i < 4; i++)
#pragma unroll
        for (int j = 0; j < 4; j++)
#pragma unroll
            for (int r = 0; r < 4; r++) acc[i][j][r] = 0.0f;

    load_stage_h(A, W, m0, n0, 0, sbase, tid); CP_COMMIT();
    load_stage_h(A, W, m0, n0, 1, sbase, tid); CP_COMMIT();

    // precompute lane-dependent ldmatrix offsets
    const uint32_t a_row = (uint32_t)(lane & 15);
    const uint32_t a_k16 = (uint32_t)(lane >> 4) * 16;
    const uint32_t b_row = (uint32_t)((lane & 7) + (lane >> 4) * 8);
    const uint32_t b_k16 = (uint32_t)((lane >> 3) & 1) * 16;

    for (int i = 0; i < 32; i++) {
        CP_WAIT1();
        __syncthreads();
        if (i + 2 < 32) load_stage_h(A, W, m0, n0, i + 2, sbase, tid);
        CP_COMMIT();

        const uint32_t ss = sbase + (uint32_t)(i % 3) * STGB;
#pragma unroll
        for (int ks = 0; ks < 2; ks++) {
            uint32_t af[4][4];
#pragma unroll
            for (int ma = 0; ma < 4; ma++) {
                uint32_t addr = ss + (uint32_t)(m_w + ma * 16 + a_row) * 80
                              + ks * 32 + a_k16;
                LDSM_X4(af[ma][0], af[ma][1], af[ma][2], af[ma][3], addr);
            }
#pragma unroll
            for (int nb = 0; nb < 2; nb++) {
                uint32_t b0, b1, b2, b3;
                uint32_t addr = ss + MATB + (uint32_t)(n_w + nb * 16 + b_row) * 80
                              + ks * 32 + b_k16;
                LDSM_X4(b0, b1, b2, b3, addr);
#pragma unroll
                for (int ma = 0; ma < 4; ma++) {
                    mma_f16_16x8x16(acc[ma][2 * nb],     af[ma], b0, b1);
                    mma_f16_16x8x16(acc[ma][2 * nb + 1], af[ma], b2, b3);
                }
            }
        }
    }

    // epilogue: regs -> global
#pragma unroll
    for (int ma = 0; ma < 4; ma++) {
        const int mA = m0 + m_w + ma * 16 + g;
#pragma unroll
        for (int na = 0; na < 4; na++) {
            const int n = n0 + n_w + na * 8 + tg * 2;
            const float b0 = bias[n], b1 = bias[n + 1];
#pragma unroll
            for (int half_i = 0; half_i < 2; half_i++) {
                const int m = mA + half_i * 8;
                float v0 = (acc[ma][na][half_i * 2 + 0] + b0) * scale;
                float v1 = (acc[ma][na][half_i * 2 + 1] + b1) * scale;
                if (qkv_layout) {
                    const int b = m >> 11;
                    const int t = m & (T_ - 1);
                    const int h = n >> 6;
                    const int d = n & (DH_ - 1);
                    *(__half2*)&Ch[(((size_t)(b * H_ + h) * T_) + t) * DH_ + d] =
                        __floats2half2_rn(v0, v1);
                } else {
                    float2 v; v.x = v0; v.y = v1;
                    *(float2*)&Cf[(size_t)m * DM_ + n] = v;
                }
            }
        }
    }
}

// Fused QKV projection: grid.z selects Q/K/V
__global__ void __launch_bounds__(256, 2) hgemm_qkv_kernel(
    const __half* __restrict__ A, const __half* __restrict__ Wbase,
    const float* __restrict__ bq, const float* __restrict__ bk,
    const float* __restrict__ bv,
    __half* __restrict__ oq, __half* __restrict__ ok, __half* __restrict__ ov)
{
    extern __shared__ char smraw[];
    const int z = blockIdx.z;
    const __half* W = Wbase + (size_t)z * NW_;
    const float* bias = (z == 0) ? bq : (z == 1) ? bk : bv;
    __half* Ch = (z == 0) ? oq : (z == 1) ? ok : ov;
    const float scale = (z == 0) ? 0.125f : 1.0f;
    gemm_core(A, W, bias, nullptr, Ch, scale, 1, smraw);
}

// Output projection (fp32 out)
__global__ void __launch_bounds__(256, 2) hgemm_out_kernel(
    const __half* __restrict__ A, const __half* __restrict__ W,
    const float* __restrict__ bias, float* __restrict__ Cf)
{
    extern __shared__ char smraw[];
    gemm_core(A, W, bias, Cf, nullptr, 1.0f, 0, smraw);
}

// ---------------------------------------------------------------------------
// Tensor-core flash attention (fp16 mma, fp32 softmax, register-resident P).
// Grid: (16, H, B); block 256 = 8 warps x 16 q rows; KV tiles 64, 3-stage
// cp.async. K frags: ldmatrix on row-major Ks. V frags: ldmatrix.trans on
// row-major Vs. P frags: rebuilt directly from QK accumulator registers.
// ---------------------------------------------------------------------------
#define AKROW  144                       // bytes per K/V smem row (64h + pad)
#define KTILE  (64 * AKROW)              // 9216 B
#define ASTG   (2 * KTILE)               // K + V per stage
#define ASMEM  (3 * ASTG)                // 55296 B

__device__ __forceinline__ void load_kv(size_t base, int c, uint32_t st, int tid)
{
#pragma unroll
    for (int j = 0; j < 2; j++) {
        int idx = tid + j * 256;             // 0..511
        int row = idx >> 3, ch = idx & 7;
        uint32_t dst = st + (uint32_t)(row * AKROW + ch * 16);
        CP16(dst,         to_global(g_k + base + (size_t)(c + row) * DH_) + ch * 16);
        CP16(dst + KTILE, to_global(g_v + base + (size_t)(c + row) * DH_) + ch * 16);
    }
}

__global__ void __launch_bounds__(256, 2) attn_kernel()
{
    extern __shared__ char ash[];
    const uint32_t abase = smem_u32(ash);

    const int tid  = threadIdx.x;
    const int w    = tid >> 5;
    const int lane = tid & 31;
    const int g    = lane >> 2;
    const int tg   = lane & 3;
    const int b  = blockIdx.z;
    const int h  = blockIdx.y;
    const int qb = (gridDim.x - 1) - blockIdx.x;   // heaviest first
    const int W0 = qb * 128 + w * 16;

    const size_t base = ((size_t)(b * H_ + h)) * T_ * DH_;

    // Q fragments (4 k-steps over d=64)
    uint32_t aq[4][4];
    {
        const uint32_t* Qg = (const uint32_t*)(g_q + base);
        const int r0 = (W0 + g) * 32;
        const int r1 = (W0 + g + 8) * 32;
#pragma unroll
        for (int ks = 0; ks < 4; ks++) {
            const int o = ks * 8 + tg;
            aq[ks][0] = Qg[r0 + o];
            aq[ks][1] = Qg[r1 + o];
            aq[ks][2] = Qg[r0 + o + 4];
            aq[ks][3] = Qg[r1 + o + 4];
        }
    }

    float o[8][4];
#pragma unroll
    for (int i = 0; i < 8; i++)
#pragma unroll
        for (int r = 0; r < 4; r++) o[i][r] = 0.0f;
    float m0 = -1e30f, m1 = -1e30f, l0 = 0.0f, l1 = 0.0f;
    const unsigned FULL = 0xFFFFFFFFu;

    // lane-dependent ldmatrix offsets
    const uint32_t kb_row = (uint32_t)((lane & 7) + (lane >> 4) * 8);   // K: key row
    const uint32_t kb_k16 = (uint32_t)((lane >> 3) & 1) * 16;           // K: d offset
    const uint32_t vb_row = (uint32_t)((lane & 7) + ((lane >> 3) & 1) * 8); // V: key row
    const uint32_t vb_d16 = (uint32_t)(lane >> 4) * 16;                 // V: d offset (bytes)

    const int ntiles = 2 * qb + 2;
    load_kv(base, 0, abase, tid);            CP_COMMIT();
    load_kv(base, 64, abase + ASTG, tid);    CP_COMMIT();

    for (int t = 0; t < ntiles; t++) {
        CP_WAIT1();
        __syncthreads();
        if (t + 2 < ntiles)
            load_kv(base, (t + 2) * 64, abase + (uint32_t)((t + 2) % 3) * ASTG, tid);
        CP_COMMIT();

        const int c = t * 64;
        if (c <= W0 + 15) {
            const uint32_t kst = abase + (uint32_t)(t % 3) * ASTG;
            const uint32_t vst = kst + KTILE;

            // ---- S = Q K^T ----
            float s[8][4];
#pragma unroll
            for (int i = 0; i < 8; i++)
#pragma unroll
                for (int r = 0; r < 4; r++) s[i][r] = 0.0f;
#pragma unroll
            for (int ks = 0; ks < 4; ks++) {
#pragma unroll
                for (int nb = 0; nb < 4; nb++) {
                    uint32_t b0, b1, b2, b3;
                    uint32_t addr = kst + (uint32_t)(nb * 16 + kb_row) * AKROW
                                  + ks * 32 + kb_k16;
                    LDSM_X4(b0, b1, b2, b3, addr);
                    mma_f16_16x8x16(s[2 * nb],     aq[ks], b0, b1);
                    mma_f16_16x8x16(s[2 * nb + 1], aq[ks], b2, b3);
                }
            }
            // ---- causal mask ----
            if (c + 63 > W0) {
#pragma unroll
                for (int na = 0; na < 8; na++) {
                    const int key0 = c + na * 8 + tg * 2;
                    if (key0 > W0 + g)          s[na][0] = -1e30f;
                    if (key0 + 1 > W0 + g)      s[na][1] = -1e30f;
                    if (key0 > W0 + g + 8)      s[na][2] = -1e30f;
                    if (key0 + 1 > W0 + g + 8)  s[na][3] = -1e30f;
                }
            }
            // ---- online softmax (rows g, g+8) ----
            float mx0 = -1e30f, mx1 = -1e30f;
#pragma unroll
            for (int na = 0; na < 8; na++) {
                mx0 = fmaxf(mx0, fmaxf(s[na][0], s[na][1]));
                mx1 = fmaxf(mx1, fmaxf(s[na][2], s[na][3]));
            }
            mx0 = fmaxf(mx0, __shfl_xor_sync(FULL, mx0, 1));
            mx0 = fmaxf(mx0, __shfl_xor_sync(FULL, mx0, 2));
            mx1 = fmaxf(mx1, __shfl_xor_sync(FULL, mx1, 1));
            mx1 = fmaxf(mx1, __shfl_xor_sync(FULL, mx1, 2));
            const float mn0 = fmaxf(m0, mx0);
            const float mn1 = fmaxf(m1, mx1);
            const float cor0 = __expf(m0 - mn0);
            const float cor1 = __expf(m1 - mn1);
            float sum0 = 0.0f, sum1 = 0.0f;
#pragma unroll
            for (int na = 0; na < 8; na++) {
                s[na][0] = __expf(s[na][0] - mn0);
                s[na][1] = __expf(s[na][1] - mn0);
                s[na][2] = __expf(s[na][2] - mn1);
                s[na][3] = __expf(s[na][3] - mn1);
                sum0 += s[na][0] + s[na][1];
                sum1 += s[na][2] + s[na][3];
            }
            sum0 += __shfl_xor_sync(FULL, sum0, 1);
            sum0 += __shfl_xor_sync(FULL, sum0, 2);
            sum1 += __shfl_xor_sync(FULL, sum1, 1);
            sum1 += __shfl_xor_sync(FULL, sum1, 2);
            l0 = l0 * cor0 + sum0;
            l1 = l1 * cor1 + sum1;
#pragma unroll
            for (int na = 0; na < 8; na++) {
                o[na][0] *= cor0; o[na][1] *= cor0;
                o[na][2] *= cor1; o[na][3] *= cor1;
            }
            m0 = mn0; m1 = mn1;

            // ---- O += P V : P frags direct from s regs, V via ldmatrix.trans ----
#pragma unroll
            for (int ks2 = 0; ks2 < 4; ks2++) {
                uint32_t pa[4];
                pa[0] = packh2(s[2 * ks2][0],     s[2 * ks2][1]);
                pa[1] = packh2(s[2 * ks2][2],     s[2 * ks2][3]);
                pa[2] = packh2(s[2 * ks2 + 1][0], s[2 * ks2 + 1][1]);
                pa[3] = packh2(s[2 * ks2 + 1][2], s[2 * ks2 + 1][3]);
#pragma unroll
                for (int nb = 0; nb < 4; nb++) {
                    uint32_t b0, b1, b2, b3;
                    uint32_t addr = vst + (uint32_t)(ks2 * 16 + vb_row) * AKROW
                                  + (uint32_t)(nb * 16) * 2 + vb_d16;
                    LDSM_X4T(b0, b1, b2, b3, addr);
                    mma_f16_16x8x16(o[2 * nb],     pa, b0, b1);
                    mma_f16_16x8x16(o[2 * nb + 1], pa, b2, b3);
                }
            }
        }
    }

    // ---- write y [B,T,DM] fp16 ----
    const float inv0 = 1.0f / l0;
    const float inv1 = 1.0f / l1;
    const int q0 = W0 + g;
    const int q1 = W0 + g + 8;
    __half* y0 = g_y + ((size_t)(b * T_ + q0)) * DM_ + h * DH_;
    __half* y1 = g_y + ((size_t)(b * T_ + q1)) * DM_ + h * DH_;
#pragma unroll
    for (int na = 0; na < 8; na++) {
        const int d = na * 8 + tg * 2;
        *(__half2*)&y0[d] = __floats2half2_rn(o[na][0] * inv0, o[na][1] * inv0);
        *(__half2*)&y1[d] = __floats2half2_rn(o[na][2] * inv1, o[na][3] * inv1);
    }
}

// ---------------------------------------------------------------------------
// Launch
// ---------------------------------------------------------------------------
extern "C" void kernel_launch(void* const* d_in, const int* in_sizes, int n_in,
                              void* d_out, int out_size)
{
    const float* x  = (const float*)d_in[0];
    const float* Wq = (const float*)d_in[1];
    const float* bq = (const float*)d_in[2];
    const float* Wk = (const float*)d_in[3];
    const float* bk = (const float*)d_in[4];
    const float* Wv = (const float*)d_in[5];
    const float* bv = (const float*)d_in[6];
    const float* Wo = (const float*)d_in[7];
    const float* bo = (const float*)d_in[8];
    float* out = (float*)d_out;

    __half *pxh, *pwh, *pq, *pk, *pv, *py;
    cudaGetSymbolAddress((void**)&pxh, g_xh);
    cudaGetSymbolAddress((void**)&pwh, g_wh);
    cudaGetSymbolAddress((void**)&pq, g_q);
    cudaGetSymbolAddress((void**)&pk, g_k);
    cudaGetSymbolAddress((void**)&pv, g_v);
    cudaGetSymbolAddress((void**)&py, g_y);

    static int attr_set = 0;
    if (!attr_set) {
        cudaFuncSetAttribute(hgemm_qkv_kernel,
                             cudaFuncAttributeMaxDynamicSharedMemorySize, GSMEM);
        cudaFuncSetAttribute(hgemm_out_kernel,
                             cudaFuncAttributeMaxDynamicSharedMemorySize, GSMEM);
        cudaFuncSetAttribute(attn_kernel,
                             cudaFuncAttributeMaxDynamicSharedMemorySize, ASMEM);
        attr_set = 1;
    }

    // fused fp32 -> fp16 (x + Wq,Wk,Wv,Wo): 3M float4 elements
    f2h_all<<<12288, 256>>>((const float4*)x, (const float4*)Wq, (const float4*)Wk,
                            (const float4*)Wv, (const float4*)Wo,
                            (__half2*)pxh, (__half2*)pwh);

    // fused QKV projections
    dim3 qgrid(DM_ / 128, M_ / 128, 3);  // (8, 64, 3)
    hgemm_qkv_kernel<<<qgrid, 256, GSMEM>>>(pxh, pwh, bq, bk, bv, pq, pk, pv);

    // attention
    dim3 agrid(T_ / 128, H_, B_);        // (16, 16, 4)
    attn_kernel<<<agrid, 256, ASMEM>>>();

    // output projection
    dim3 ggrid(DM_ / 128, M_ / 128);     // (8, 64)
    hgemm_out_kernel<<<ggrid, 256, GSMEM>>>(py, pwh + 3 * (size_t)NW_, bo, out);
}

// round 12
// speedup vs baseline: 13.2385x; 1.0388x over previous
#include <cuda_runtime.h>
#include <cuda_fp16.h>
#include <stdint.h>
#include <math.h>

// Problem constants
#define B_   4
#define T_   2048
#define DM_  1024
#define H_   16
#define DH_  64
#define M_   (B_ * T_)
#define NW_  (DM_ * DM_)

// Scratch (device globals: allocation-free rule)
__device__ __half g_xh[M_ * DM_];        // fp16 x
__device__ __half g_wh[4 * NW_];         // fp16 Wq,Wk,Wv,Wo
__device__ __half g_q[M_ * DM_];         // [B,H,T,DH], pre-scaled by 1/8
__device__ __half g_k[M_ * DM_];
__device__ __half g_v[M_ * DM_];
__device__ __half g_y[M_ * DM_];         // attention out, [B,T,DM]

// ---------------------------------------------------------------------------
// Helpers
// ---------------------------------------------------------------------------
__device__ __forceinline__ uint32_t smem_u32(const void* p) {
    uint32_t a;
    asm("{ .reg .u64 t; cvta.to.shared.u64 t, %1; cvt.u32.u64 %0, t; }"
        : "=r"(a) : "l"(p));
    return a;
}

__device__ __forceinline__ const char* to_global(const void* p) {
    uint64_t g;
    asm("cvta.to.global.u64 %0, %1;" : "=l"(g) : "l"(p));
    return (const char*)g;
}

__device__ __forceinline__ void mma_f16_16x8x16(
    float* c, const uint32_t* a, uint32_t b0, uint32_t b1)
{
    asm volatile(
        "mma.sync.aligned.m16n8k16.row.col.f32.f16.f16.f32 "
        "{%0,%1,%2,%3}, {%4,%5,%6,%7}, {%8,%9}, {%0,%1,%2,%3};"
        : "+f"(c[0]), "+f"(c[1]), "+f"(c[2]), "+f"(c[3])
        : "r"(a[0]), "r"(a[1]), "r"(a[2]), "r"(a[3]), "r"(b0), "r"(b1));
}

#define LDSM_X4(r0, r1, r2, r3, a) \
    asm volatile("ldmatrix.sync.aligned.m8n8.x4.shared.b16 {%0,%1,%2,%3}, [%4];" \
                 : "=r"(r0), "=r"(r1), "=r"(r2), "=r"(r3) : "r"(a))
#define LDSM_X4T(r0, r1, r2, r3, a) \
    asm volatile("ldmatrix.sync.aligned.m8n8.x4.trans.shared.b16 {%0,%1,%2,%3}, [%4];" \
                 : "=r"(r0), "=r"(r1), "=r"(r2), "=r"(r3) : "r"(a))
#define CP16(dst, src) \
    asm volatile("cp.async.cg.shared.global [%0], [%1], 16;" :: "r"(dst), "l"(src) : "memory")
#define CP_COMMIT() asm volatile("cp.async.commit_group;" ::: "memory")
#define CP_WAIT1()  asm volatile("cp.async.wait_group 1;" ::: "memory")

__device__ __forceinline__ uint32_t packh2(float a, float b) {
    __half2 h = __floats2half2_rn(a, b);
    return *(uint32_t*)&h;
}

// ---------------------------------------------------------------------------
// Fused fp32 -> fp16 conversion (x + all 4 weights in one launch)
// ---------------------------------------------------------------------------
__global__ void __launch_bounds__(256) f2h_all(
    const float4* __restrict__ x,  const float4* __restrict__ wq,
    const float4* __restrict__ wk, const float4* __restrict__ wv,
    const float4* __restrict__ wo, __half2* __restrict__ xh,
    __half2* __restrict__ wh)
{
    int i = blockIdx.x * 256 + threadIdx.x;
    const float4* src;
    __half2* dst;
    if (i < 2097152) {                       // x: 8M floats = 2M float4
        src = x + i;
        dst = xh + 2 * (size_t)i;
    } else {
        int j = i - 2097152;                 // weights: 4 x 256K float4
        int w = j >> 18, off = j & 0x3FFFF;
        const float4* ws = (w == 0) ? wq : (w == 1) ? wk : (w == 2) ? wv : wo;
        src = ws + off;
        dst = wh + (size_t)w * 524288 + 2 * (size_t)off;
    }
    float4 v = *src;
    dst[0] = __floats2half2_rn(v.x, v.y);
    dst[1] = __floats2half2_rn(v.z, v.w);
}

// ---------------------------------------------------------------------------
// fp16 mma GEMM core: C[M,N] = (A[M,K] @ W[N,K]^T + bias[N]) * scale
// CTA tile 128x128, 8 warps (2m x 4n), warp tile 64x32, m16n8k16.
// BK=64, 3-stage cp.async (16 iters -> half the barriers of BK=32),
// explicit fragment double-buffering across the 4 k16-steps.
// SMEM rows 144B -> ldmatrix conflict-free (8-row start banks 0,4,..,28).
// ---------------------------------------------------------------------------
#define MATB  (128 * 144)                // 18432 B per padded 128x64 half tile
#define STGB  (2 * MATB)                 // A + W per stage = 36864 B
#define GSMEM (3 * STGB)                 // 110592 B

__device__ __forceinline__ void load_stage_h(
    const __half* __restrict__ A, const __half* __restrict__ W,
    int m0, int n0, int chunk, uint32_t sbase, int tid)
{
    const uint32_t st = sbase + (uint32_t)(chunk % 3) * STGB;
#pragma unroll
    for (int j = 0; j < 4; j++) {
        int idx = tid + j * 256;             // 0..1023
        int row = idx >> 3;                  // 0..127
        int ch  = idx & 7;                   // 16B chunk in 128B row
        uint32_t dst = st + (uint32_t)(row * 144 + ch * 16);
        CP16(dst, to_global(A + (size_t)(m0 + row) * DM_ + chunk * 64) + ch * 16);
        CP16(dst + MATB, to_global(W + (size_t)(n0 + row) * DM_ + chunk * 64) + ch * 16);
    }
}

__device__ __forceinline__ void gemm_core(
    const __half* __restrict__ A, const __half* __restrict__ W,
    const float* __restrict__ bias, float* __restrict__ Cf,
    __half* __restrict__ Ch, float scale, int qkv_layout, char* smraw)
{
    const uint32_t sbase = smem_u32(smraw);
    const int tid  = threadIdx.x;
    const int wid  = tid >> 5;
    const int lane = tid & 31;
    const int g    = lane >> 2;
    const int tg   = lane & 3;
    const int m0 = blockIdx.y * 128;
    const int n0 = blockIdx.x * 128;
    const int m_w = (wid >> 2) * 64;
    const int n_w = (wid & 3) * 32;

    float acc[4][4][4];
#pragma unroll
    for (int i = 0; i < 4; i++)
#pragma unroll
        for (int j = 0; j < 4; j++)
#pragma unroll
            for (int r = 0; r < 4; r++) acc[i][j][r] = 0.0f;

    load_stage_h(A, W, m0, n0, 0, sbase, tid); CP_COMMIT();
    load_stage_h(A, W, m0, n0, 1, sbase, tid); CP_COMMIT();

    // lane-dependent ldmatrix offsets (within a stage)
    const uint32_t a_off = (uint32_t)(m_w + (lane & 15)) * 144 + (uint32_t)(lane >> 4) * 16;
    const uint32_t b_off = (uint32_t)MATB
                         + (uint32_t)(n_w + (lane & 7) + (lane >> 4) * 8) * 144
                         + (uint32_t)((lane >> 3) & 1) * 16;

    uint32_t af[2][4][4], bf[2][2][4];

    for (int i = 0; i < 16; i++) {
        CP_WAIT1();
        __syncthreads();
        if (i + 2 < 16) load_stage_h(A, W, m0, n0, i + 2, sbase, tid);
        CP_COMMIT();

        const uint32_t ss = sbase + (uint32_t)(i % 3) * STGB;

        // preload fragments for ks = 0
#pragma unroll
        for (int ma = 0; ma < 4; ma++) {
            uint32_t addr = ss + a_off + (uint32_t)(ma * 16) * 144;
            LDSM_X4(af[0][ma][0], af[0][ma][1], af[0][ma][2], af[0][ma][3], addr);
        }
#pragma unroll
        for (int nb = 0; nb < 2; nb++) {
            uint32_t addr = ss + b_off + (uint32_t)(nb * 16) * 144;
            LDSM_X4(bf[0][nb][0], bf[0][nb][1], bf[0][nb][2], bf[0][nb][3], addr);
        }

#pragma unroll
        for (int ks = 0; ks < 4; ks++) {
            const int cur = ks & 1, nxt = cur ^ 1;
            if (ks < 3) {
                const uint32_t ko = (uint32_t)((ks + 1) * 32);
#pragma unroll
                for (int ma = 0; ma < 4; ma++) {
                    uint32_t addr = ss + a_off + (uint32_t)(ma * 16) * 144 + ko;
                    LDSM_X4(af[nxt][ma][0], af[nxt][ma][1], af[nxt][ma][2], af[nxt][ma][3], addr);
                }
#pragma unroll
                for (int nb = 0; nb < 2; nb++) {
                    uint32_t addr = ss + b_off + (uint32_t)(nb * 16) * 144 + ko;
                    LDSM_X4(bf[nxt][nb][0], bf[nxt][nb][1], bf[nxt][nb][2], bf[nxt][nb][3], addr);
                }
            }
#pragma unroll
            for (int nb = 0; nb < 2; nb++)
#pragma unroll
                for (int ma = 0; ma < 4; ma++) {
                    mma_f16_16x8x16(acc[ma][2 * nb],     af[cur][ma], bf[cur][nb][0], bf[cur][nb][1]);
                    mma_f16_16x8x16(acc[ma][2 * nb + 1], af[cur][ma], bf[cur][nb][2], bf[cur][nb][3]);
                }
        }
    }

    // epilogue: regs -> global
#pragma unroll
    for (int ma = 0; ma < 4; ma++) {
        const int mA = m0 + m_w + ma * 16 + g;
#pragma unroll
        for (int na = 0; na < 4; na++) {
            const int n = n0 + n_w + na * 8 + tg * 2;
            const float b0 = bias[n], b1 = bias[n + 1];
#pragma unroll
            for (int half_i = 0; half_i < 2; half_i++) {
                const int m = mA + half_i * 8;
                float v0 = (acc[ma][na][half_i * 2 + 0] + b0) * scale;
                float v1 = (acc[ma][na][half_i * 2 + 1] + b1) * scale;
                if (qkv_layout) {
                    const int b = m >> 11;
                    const int t = m & (T_ - 1);
                    const int h = n >> 6;
                    const int d = n & (DH_ - 1);
                    *(__half2*)&Ch[(((size_t)(b * H_ + h) * T_) + t) * DH_ + d] =
                        __floats2half2_rn(v0, v1);
                } else {
                    float2 v; v.x = v0; v.y = v1;
                    *(float2*)&Cf[(size_t)m * DM_ + n] = v;
                }
            }
        }
    }
}

// Fused QKV projection: grid.z selects Q/K/V
__global__ void __launch_bounds__(256, 2) hgemm_qkv_kernel(
    const __half* __restrict__ A, const __half* __restrict__ Wbase,
    const float* __restrict__ bq, const float* __restrict__ bk,
    const float* __restrict__ bv,
    __half* __restrict__ oq, __half* __restrict__ ok, __half* __restrict__ ov)
{
    extern __shared__ char smraw[];
    const int z = blockIdx.z;
    const __half* W = Wbase + (size_t)z * NW_;
    const float* bias = (z == 0) ? bq : (z == 1) ? bk : bv;
    __half* Ch = (z == 0) ? oq : (z == 1) ? ok : ov;
    const float scale = (z == 0) ? 0.125f : 1.0f;
    gemm_core(A, W, bias, nullptr, Ch, scale, 1, smraw);
}

// Output projection (fp32 out)
__global__ void __launch_bounds__(256, 2) hgemm_out_kernel(
    const __half* __restrict__ A, const __half* __restrict__ W,
    const float* __restrict__ bias, float* __restrict__ Cf)
{
    extern __shared__ char smraw[];
    gemm_core(A, W, bias, Cf, nullptr, 1.0f, 0, smraw);
}

// ---------------------------------------------------------------------------
// Tensor-core flash attention (fp16 mma, fp32 softmax, register-resident P).
// Grid: (16, H, B); block 256 = 8 warps x 16 q rows; KV tiles 64, 3-stage
// cp.async. K frags: ldmatrix on row-major Ks. V frags: ldmatrix.trans.
// ---------------------------------------------------------------------------
#define AKROW  144
#define KTILE  (64 * AKROW)
#define ASTG   (2 * KTILE)
#define ASMEM  (3 * ASTG)

__device__ __forceinline__ void load_kv(size_t base, int c, uint32_t st, int tid)
{
#pragma unroll
    for (int j = 0; j < 2; j++) {
        int idx = tid + j * 256;
        int row = idx >> 3, ch = idx & 7;
        uint32_t dst = st + (uint32_t)(row * AKROW + ch * 16);
        CP16(dst,         to_global(g_k + base + (size_t)(c + row) * DH_) + ch * 16);
        CP16(dst + KTILE, to_global(g_v + base + (size_t)(c + row) * DH_) + ch * 16);
    }
}

__global__ void __launch_bounds__(256, 2) attn_kernel()
{
    extern __shared__ char ash[];
    const uint32_t abase = smem_u32(ash);

    const int tid  = threadIdx.x;
    const int w    = tid >> 5;
    const int lane = tid & 31;
    const int g    = lane >> 2;
    const int tg   = lane & 3;
    const int b  = blockIdx.z;
    const int h  = blockIdx.y;
    const int qb = (gridDim.x - 1) - blockIdx.x;
    const int W0 = qb * 128 + w * 16;

    const size_t base = ((size_t)(b * H_ + h)) * T_ * DH_;

    uint32_t aq[4][4];
    {
        const uint32_t* Qg = (const uint32_t*)(g_q + base);
        const int r0 = (W0 + g) * 32;
        const int r1 = (W0 + g + 8) * 32;
#pragma unroll
        for (int ks = 0; ks < 4; ks++) {
            const int o = ks * 8 + tg;
            aq[ks][0] = Qg[r0 + o];
            aq[ks][1] = Qg[r1 + o];
            aq[ks][2] = Qg[r0 + o + 4];
            aq[ks][3] = Qg[r1 + o + 4];
        }
    }

    float o[8][4];
#pragma unroll
    for (int i = 0; i < 8; i++)
#pragma unroll
        for (int r = 0; r < 4; r++) o[i][r] = 0.0f;
    float m0 = -1e30f, m1 = -1e30f, l0 = 0.0f, l1 = 0.0f;
    const unsigned FULL = 0xFFFFFFFFu;

    const uint32_t kb_row = (uint32_t)((lane & 7) + (lane >> 4) * 8);
    const uint32_t kb_k16 = (uint32_t)((lane >> 3) & 1) * 16;
    const uint32_t vb_row = (uint32_t)((lane & 7) + ((lane >> 3) & 1) * 8);
    const uint32_t vb_d16 = (uint32_t)(lane >> 4) * 16;

    const int ntiles = 2 * qb + 2;
    load_kv(base, 0, abase, tid);            CP_COMMIT();
    load_kv(base, 64, abase + ASTG, tid);    CP_COMMIT();

    for (int t = 0; t < ntiles; t++) {
        CP_WAIT1();
        __syncthreads();
        if (t + 2 < ntiles)
            load_kv(base, (t + 2) * 64, abase + (uint32_t)((t + 2) % 3) * ASTG, tid);
        CP_COMMIT();

        const int c = t * 64;
        if (c <= W0 + 15) {
            const uint32_t kst = abase + (uint32_t)(t % 3) * ASTG;
            const uint32_t vst = kst + KTILE;

            float s[8][4];
#pragma unroll
            for (int i = 0; i < 8; i++)
#pragma unroll
                for (int r = 0; r < 4; r++) s[i][r] = 0.0f;
#pragma unroll
            for (int ks = 0; ks < 4; ks++) {
#pragma unroll
                for (int nb = 0; nb < 4; nb++) {
                    uint32_t b0, b1, b2, b3;
                    uint32_t addr = kst + (uint32_t)(nb * 16 + kb_row) * AKROW
                                  + ks * 32 + kb_k16;
                    LDSM_X4(b0, b1, b2, b3, addr);
                    mma_f16_16x8x16(s[2 * nb],     aq[ks], b0, b1);
                    mma_f16_16x8x16(s[2 * nb + 1], aq[ks], b2, b3);
                }
            }
            if (c + 63 > W0) {
#pragma unroll
                for (int na = 0; na < 8; na++) {
                    const int key0 = c + na * 8 + tg * 2;
                    if (key0 > W0 + g)          s[na][0] = -1e30f;
                    if (key0 + 1 > W0 + g)      s[na][1] = -1e30f;
                    if (key0 > W0 + g + 8)      s[na][2] = -1e30f;
                    if (key0 + 1 > W0 + g + 8)  s[na][3] = -1e30f;
                }
            }
            float mx0 = -1e30f, mx1 = -1e30f;
#pragma unroll
            for (int na = 0; na < 8; na++) {
                mx0 = fmaxf(mx0, fmaxf(s[na][0], s[na][1]));
                mx1 = fmaxf(mx1, fmaxf(s[na][2], s[na][3]));
            }
            mx0 = fmaxf(mx0, __shfl_xor_sync(FULL, mx0, 1));
            mx0 = fmaxf(mx0, __shfl_xor_sync(FULL, mx0, 2));
            mx1 = fmaxf(mx1, __shfl_xor_sync(FULL, mx1, 1));
            mx1 = fmaxf(mx1, __shfl_xor_sync(FULL, mx1, 2));
            const float mn0 = fmaxf(m0, mx0);
            const float mn1 = fmaxf(m1, mx1);
            const float cor0 = __expf(m0 - mn0);
            const float cor1 = __expf(m1 - mn1);
            float sum0 = 0.0f, sum1 = 0.0f;
#pragma unroll
            for (int na = 0; na < 8; na++) {
                s[na][0] = __expf(s[na][0] - mn0);
                s[na][1] = __expf(s[na][1] - mn0);
                s[na][2] = __expf(s[na][2] - mn1);
                s[na][3] = __expf(s[na][3] - mn1);
                sum0 += s[na][0] + s[na][1];
                sum1 += s[na][2] + s[na][3];
            }
            sum0 += __shfl_xor_sync(FULL, sum0, 1);
            sum0 += __shfl_xor_sync(FULL, sum0, 2);
            sum1 += __shfl_xor_sync(FULL, sum1, 1);
            sum1 += __shfl_xor_sync(FULL, sum1, 2);
            l0 = l0 * cor0 + sum0;
            l1 = l1 * cor1 + sum1;
#pragma unroll
            for (int na = 0; na < 8; na++) {
                o[na][0] *= cor0; o[na][1] *= cor0;
                o[na][2] *= cor1; o[na][3] *= cor1;
            }
            m0 = mn0; m1 = mn1;

#pragma unroll
            for (int ks2 = 0; ks2 < 4; ks2++) {
                uint32_t pa[4];
                pa[0] = packh2(s[2 * ks2][0],     s[2 * ks2][1]);
                pa[1] = packh2(s[2 * ks2][2],     s[2 * ks2][3]);
                pa[2] = packh2(s[2 * ks2 + 1][0], s[2 * ks2 + 1][1]);
                pa[3] = packh2(s[2 * ks2 + 1][2], s[2 * ks2 + 1][3]);
#pragma unroll
                for (int nb = 0; nb < 4; nb++) {
                    uint32_t b0, b1, b2, b3;
                    uint32_t addr = vst + (uint32_t)(ks2 * 16 + vb_row) * AKROW
                                  + (uint32_t)(nb * 16) * 2 + vb_d16;
                    LDSM_X4T(b0, b1, b2, b3, addr);
                    mma_f16_16x8x16(o[2 * nb],     pa, b0, b1);
                    mma_f16_16x8x16(o[2 * nb + 1], pa, b2, b3);
                }
            }
        }
    }

    const float inv0 = 1.0f / l0;
    const float inv1 = 1.0f / l1;
    const int q0 = W0 + g;
    const int q1 = W0 + g + 8;
    __half* y0 = g_y + ((size_t)(b * T_ + q0)) * DM_ + h * DH_;
    __half* y1 = g_y + ((size_t)(b * T_ + q1)) * DM_ + h * DH_;
#pragma unroll
    for (int na = 0; na < 8; na++) {
        const int d = na * 8 + tg * 2;
        *(__half2*)&y0[d] = __floats2half2_rn(o[na][0] * inv0, o[na][1] * inv0);
        *(__half2*)&y1[d] = __floats2half2_rn(o[na][2] * inv1, o[na][3] * inv1);
    }
}

// ---------------------------------------------------------------------------
// Launch
// ---------------------------------------------------------------------------
extern "C" void kernel_launch(void* const* d_in, const int* in_sizes, int n_in,
                              void* d_out, int out_size)
{
    const float* x  = (const float*)d_in[0];
    const float* Wq = (const float*)d_in[1];
    const float* bq = (const float*)d_in[2];
    const float* Wk = (const float*)d_in[3];
    const float* bk = (const float*)d_in[4];
    const float* Wv = (const float*)d_in[5];
    const float* bv = (const float*)d_in[6];
    const float* Wo = (const float*)d_in[7];
    const float* bo = (const float*)d_in[8];
    float* out = (float*)d_out;

    __half *pxh, *pwh, *pq, *pk, *pv, *py;
    cudaGetSymbolAddress((void**)&pxh, g_xh);
    cudaGetSymbolAddress((void**)&pwh, g_wh);
    cudaGetSymbolAddress((void**)&pq, g_q);
    cudaGetSymbolAddress((void**)&pk, g_k);
    cudaGetSymbolAddress((void**)&pv, g_v);
    cudaGetSymbolAddress((void**)&py, g_y);

    static int attr_set = 0;
    if (!attr_set) {
        cudaFuncSetAttribute(hgemm_qkv_kernel,
                             cudaFuncAttributeMaxDynamicSharedMemorySize, GSMEM);
        cudaFuncSetAttribute(hgemm_out_kernel,
                             cudaFuncAttributeMaxDynamicSharedMemorySize, GSMEM);
        cudaFuncSetAttribute(attn_kernel,
                             cudaFuncAttributeMaxDynamicSharedMemorySize, ASMEM);
        attr_set = 1;
    }

    f2h_all<<<12288, 256>>>((const float4*)x, (const float4*)Wq, (const float4*)Wk,
                            (const float4*)Wv, (const float4*)Wo,
                            (__half2*)pxh, (__half2*)pwh);

    dim3 qgrid(DM_ / 128, M_ / 128, 3);  // (8, 64, 3)
    hgemm_qkv_kernel<<<qgrid, 256, GSMEM>>>(pxh, pwh, bq, bk, bv, pq, pk, pv);

    dim3 agrid(T_ / 128, H_, B_);        // (16, 16, 4)
    attn_kernel<<<agrid, 256, ASMEM>>>();

    dim3 ggrid(DM_ / 128, M_ / 128);     // (8, 64)
    hgemm_out_kernel<<<ggrid, 256, GSMEM>>>(py, pwh + 3 * (size_t)NW_, bo, out);
}